// round 15
// baseline (speedup 1.0000x reference)
#include <cuda_runtime.h>
#include <cuda_fp16.h>
#include <cstdint>

#define IN_F   2048
#define OUT_F  8192
#define NROWS  8192
#define NBLK   4096   // 64 in-blocks (32 cols) x 64 out-blocks (128 rows)
#define TOPK   410
#define NITEMS 2048   // 64 ng x 32 m-tiles (256 rows each)
#define NCTA   148    // persistent, 1 per SM

// ---------------------------------------------------------------------------
// Scratch (static device memory; no runtime allocation)
// ---------------------------------------------------------------------------
__device__ float g_scores[NBLK];
__device__ int   g_klist[64 * 64];
__device__ int   g_kcount[64];
__device__ int   g_ngord[64];
__device__ int   g_selkb[TOPK];
__device__ int   g_selng[TOPK];
__device__ __align__(16) unsigned short g_Xh[(size_t)NROWS * IN_F];
__device__ __align__(16) unsigned short g_Wh[(size_t)OUT_F * IN_F];

// ---------------------------------------------------------------------------
// Helpers
// ---------------------------------------------------------------------------
__device__ __forceinline__ uint32_t smem_u32(const void* p) {
    uint32_t r;
    asm("{ .reg .u64 t; cvta.to.shared.u64 t, %1; cvt.u32.u64 %0, t; }"
        : "=r"(r) : "l"(p));
    return r;
}

__device__ __forceinline__ void cp_async16(uint32_t dst, const void* src) {
    asm volatile("cp.async.cg.shared.global [%0], [%1], 16;" :: "r"(dst), "l"(src));
}

__device__ __forceinline__ void ldsm_x4(uint32_t* r, uint32_t addr) {
    asm volatile("ldmatrix.sync.aligned.m8n8.x4.shared.b16 {%0,%1,%2,%3}, [%4];"
                 : "=r"(r[0]), "=r"(r[1]), "=r"(r[2]), "=r"(r[3]) : "r"(addr));
}
__device__ __forceinline__ void mma16816(float* d, const uint32_t* a, const uint32_t* b) {
    asm volatile(
        "mma.sync.aligned.m16n8k16.row.col.f32.f16.f16.f32 "
        "{%0,%1,%2,%3}, {%4,%5,%6,%7}, {%8,%9}, {%0,%1,%2,%3};"
        : "+f"(d[0]), "+f"(d[1]), "+f"(d[2]), "+f"(d[3])
        : "r"(a[0]), "r"(a[1]), "r"(a[2]), "r"(a[3]), "r"(b[0]), "r"(b[1]));
}

// Panel: rows x 64B (32 fp16), two rows per 128B line.
// 16B chunk (row, c) at: off = (row>>1)*128 + ((((row&1)<<2)+c) ^ ((row>>1)&7))*16
__device__ __forceinline__ uint32_t panel_off(int row, int c) {
    return (uint32_t)((row >> 1) * 128 +
                      (((((row & 1) << 2) + c) ^ ((row >> 1) & 7)) << 4));
}

// ---------------------------------------------------------------------------
// Kernel A (fused prep): blocks [0,8192) convert X rows to fp16;
// blocks [8192,12288) compute per-block sum of |W|.
// ---------------------------------------------------------------------------
__global__ __launch_bounds__(256)
void prep1(const float* __restrict__ X, const float* __restrict__ W) {
    const int b = blockIdx.x;
    const int t = threadIdx.x;
    if (b < 8192) {
        const size_t idx = (size_t)b * 256 + t;
        const float4* s4 = reinterpret_cast<const float4*>(X) + idx * 2;
        float4 a = s4[0], bb = s4[1];
        __half2 h0 = __floats2half2_rn(a.x, a.y);
        __half2 h1 = __floats2half2_rn(a.z, a.w);
        __half2 h2 = __floats2half2_rn(bb.x, bb.y);
        __half2 h3 = __floats2half2_rn(bb.z, bb.w);
        uint4 o;
        o.x = *reinterpret_cast<uint32_t*>(&h0);
        o.y = *reinterpret_cast<uint32_t*>(&h1);
        o.z = *reinterpret_cast<uint32_t*>(&h2);
        o.w = *reinterpret_cast<uint32_t*>(&h3);
        reinterpret_cast<uint4*>(g_Xh)[idx] = o;
    } else {
        const int blk = b - 8192;
        const int i = blk >> 6;      // in-block
        const int j = blk & 63;      // out-block
        const int row = j * 128 + (t >> 1);
        const float4* p = reinterpret_cast<const float4*>(
            W + (size_t)row * IN_F + i * 32 + (t & 1) * 16);
        float s = 0.f;
#pragma unroll
        for (int c = 0; c < 4; ++c) {
            float4 v = p[c];
            s += fabsf(v.x) + fabsf(v.y) + fabsf(v.z) + fabsf(v.w);
        }
        s += __shfl_down_sync(0xFFFFFFFFu, s, 1);
        __shared__ float red[128];
        if ((t & 1) == 0) red[t >> 1] = s;
        __syncthreads();
        for (int off = 64; off > 0; off >>= 1) {
            if (t < off) red[t] += red[t + off];
            __syncthreads();
        }
        if (t == 0) g_scores[blk] = red[0];
    }
}

// ---------------------------------------------------------------------------
// Kernel B: radix top-k select; emits g_klist/g_kcount, flat g_selkb/g_selng,
// heavy-first g_ngord.
// ---------------------------------------------------------------------------
__global__ __launch_bounds__(1024)
void topk_select() {
    __shared__ uint32_t       keys[NBLK];
    __shared__ uint32_t       wsum[32];
    __shared__ uint32_t       s_prefix, s_k;
    __shared__ int            s_w0tot;
    __shared__ unsigned char  sel[NBLK];
    const int t    = threadIdx.x;
    const int lane = t & 31;
    const int wid  = t >> 5;

    for (int p = t; p < NBLK; p += 1024) {
        keys[p] = __float_as_uint(g_scores[p]);
        sel[p]  = 0;
    }
    if (t == 0) { s_prefix = 0; s_k = TOPK; }
    __syncthreads();

    for (int bit = 30; bit >= 0; --bit) {
        uint32_t prefix = s_prefix;
        uint32_t c = 0;
        for (int p = t; p < NBLK; p += 1024) {
            uint32_t key  = keys[p];
            bool cand = ((key ^ prefix) >> (bit + 1)) == 0;
            c += (cand && ((key >> bit) & 1u)) ? 1u : 0u;
        }
        c = __reduce_add_sync(0xFFFFFFFFu, c);
        if (lane == 0) wsum[wid] = c;
        __syncthreads();
        if (t == 0) {
            uint32_t tot = 0;
#pragma unroll
            for (int w = 0; w < 32; ++w) tot += wsum[w];
            if (tot >= s_k) s_prefix |= (1u << bit);
            else            s_k -= tot;
        }
        __syncthreads();
    }

    const uint32_t T     = s_prefix;
    const uint32_t kneed = s_k;

    uint32_t e[4], tsum = 0;
#pragma unroll
    for (int j = 0; j < 4; ++j) {
        e[j] = (keys[t * 4 + j] == T) ? 1u : 0u;
        tsum += e[j];
    }
    uint32_t x = tsum;
#pragma unroll
    for (int d = 1; d < 32; d <<= 1) {
        uint32_t y = __shfl_up_sync(0xFFFFFFFFu, x, d);
        if (lane >= d) x += y;
    }
    const uint32_t excl = x - tsum;
    if (lane == 31) wsum[wid] = x;
    __syncthreads();
    if (t == 0) {
        uint32_t run = 0;
#pragma unroll
        for (int w = 0; w < 32; ++w) { uint32_t tmp = wsum[w]; wsum[w] = run; run += tmp; }
    }
    __syncthreads();

    uint32_t r = wsum[wid] + excl;
#pragma unroll
    for (int j = 0; j < 4; ++j) {
        uint32_t key = keys[t * 4 + j];
        if (key > T) sel[t * 4 + j] = 1;
        if (e[j]) { if (r < kneed) sel[t * 4 + j] = 1; r++; }
    }
    __syncthreads();

    if (t < 64) {
        int c = 0;
        for (int i = 0; i < 64; ++i)
            if (sel[i * 64 + t]) g_klist[t * 64 + (c++)] = i;
        g_kcount[t] = c;
    }
    __syncthreads();

    // flat selected-block list (for selective W convert)
    {
        int v = (t < 64) ? g_kcount[t] : 0;
        int xx = v;
#pragma unroll
        for (int d = 1; d < 32; d <<= 1) {
            int y = __shfl_up_sync(0xFFFFFFFFu, xx, d);
            if (lane >= d) xx += y;
        }
        if (t == 31) s_w0tot = xx;
        __syncthreads();
        if (t < 64) {
            int base = (t >= 32) ? s_w0tot : 0;
            int off = base + xx - v;
            for (int i = 0; i < v; ++i) {
                g_selng[off + i] = t;
                g_selkb[off + i] = g_klist[t * 64 + i];
            }
        }
    }
    __syncthreads();

    // heavy-first n-group order
    if (t < 64) {
        const int myc = g_kcount[t];
        int rank = 0;
        for (int i = 0; i < 64; ++i) {
            const int ci = g_kcount[i];
            rank += (ci > myc) || (ci == myc && i < t);
        }
        g_ngord[rank] = t;
    }
}

// ---------------------------------------------------------------------------
// Kernel C: convert ONLY selected W blocks to fp16 (grid = TOPK)
// ---------------------------------------------------------------------------
__global__ __launch_bounds__(256)
void convert_w_sel(const float* __restrict__ W) {
    const int kb = g_selkb[blockIdx.x];
    const int ng = g_selng[blockIdx.x];
    const int tid = threadIdx.x;
#pragma unroll
    for (int u = 0; u < 4; ++u) {
        const int q   = tid + (u << 8);
        const int row = q >> 3;
        const int cc  = q & 7;
        const size_t grow = (size_t)(ng * 128 + row);
        float4 v = *reinterpret_cast<const float4*>(W + grow * IN_F + kb * 32 + cc * 4);
        __half2 h0 = __floats2half2_rn(v.x, v.y);
        __half2 h1 = __floats2half2_rn(v.z, v.w);
        uint2 o;
        o.x = *reinterpret_cast<uint32_t*>(&h0);
        o.y = *reinterpret_cast<uint32_t*>(&h1);
        *reinterpret_cast<uint2*>(g_Wh + grow * IN_F + kb * 32 + cc * 4) = o;
    }
}

// ---------------------------------------------------------------------------
// Kernel D: PERSISTENT block-sparse GEMM, fp16 mma.sync, fp32 accum.
// CTA tile 256x128 (M=256!): 25% fewer LDGSTS per output. 8 warps (256 thr),
// warp tile 64x64 (wm=wid&3, wn=wid>>2). 148 persistent CTAs; items:
// item -> ng = g_ngord[item>>5], mt = item&31 (m0 = mt*256). Continuous
// cp.async cursor across item boundaries, 4 stages x 24KB.
// ---------------------------------------------------------------------------
#define A_BYTES     16384
#define STAGE_BYTES 24576
#define NSTAGE      4
#define SMEM_TOTAL  (STAGE_BYTES * NSTAGE)

__device__ __forceinline__ void load_tiles(uint32_t stage_base,
                                           const uint4* __restrict__ XH,
                                           const uint4* __restrict__ WH,
                                           int m0, int n0, int kb, int tid) {
    const int kb4 = kb * 4;
    // A: 256 rows x 4 chunks = 1024 chunks
#pragma unroll
    for (int j = 0; j < 4; ++j) {
        int q   = tid + (j << 8);
        int row = q >> 2;
        int c   = q & 3;
        uint32_t off = panel_off(row, c);
        cp_async16(stage_base + off, XH + (size_t)(m0 + row) * 256 + kb4 + c);
    }
    // B: 128 rows x 4 chunks = 512 chunks
#pragma unroll
    for (int j = 0; j < 2; ++j) {
        int q   = tid + (j << 8);
        int row = q >> 2;
        int c   = q & 3;
        uint32_t off = panel_off(row, c);
        cp_async16(stage_base + A_BYTES + off, WH + (size_t)(n0 + row) * 256 + kb4 + c);
    }
}

__global__ __launch_bounds__(256, 1)
void mma_kernel(const float* __restrict__ Bias, float* __restrict__ out) {
    extern __shared__ char smem[];
    const uint32_t sb  = smem_u32(smem);
    const int tid  = threadIdx.x;
    const int wid  = tid >> 5;
    const int lane = tid & 31;
    const int b    = blockIdx.x;

    const int wm = wid & 3;        // m quarter (64 rows of 256)
    const int wn = wid >> 2;       // n half (64 cols of 128)

    // per-lane fragment offsets (item-independent)
    uint32_t aOff[4][2];
#pragma unroll
    for (int i = 0; i < 4; ++i) {
        const int rowA = (wm << 6) + (i << 4) + (lane & 15);
#pragma unroll
        for (int s16 = 0; s16 < 2; ++s16)
            aOff[i][s16] = panel_off(rowA, (s16 << 1) + (lane >> 4));
    }
    uint32_t bOff[4][2];
#pragma unroll
    for (int j2 = 0; j2 < 4; ++j2) {
        const int rowB = (wn << 6) + (j2 << 4) + (((lane >> 4) & 1) << 3) + (lane & 7);
#pragma unroll
        for (int s16 = 0; s16 < 2; ++s16)
            bOff[j2][s16] = panel_off(rowB, (s16 << 1) + ((lane >> 3) & 1));
    }

    const uint4* XH = reinterpret_cast<const uint4*>(g_Xh);
    const uint4* WH = reinterpret_cast<const uint4*>(g_Wh);

    // ---- load cursor (uniform across threads) ----
    int jL    = 0;
    int itemL = b;
    int ngL   = g_ngord[itemL >> 5];
    int mtL   = itemL & 31;
    int cntL  = g_kcount[ngL];
    int stepL = 0;
    int slotL = 0;

    auto load_step = [&]() {
        while (stepL >= cntL) {
            jL++;
            itemL = b + jL * NCTA;
            if (itemL >= NITEMS) return;
            ngL  = g_ngord[itemL >> 5];
            mtL  = itemL & 31;
            cntL = g_kcount[ngL];
            stepL = 0;
        }
        const int kb = g_klist[(ngL << 6) + stepL];
        load_tiles(sb + (slotL & 3) * STAGE_BYTES, XH, WH, mtL << 8, ngL << 7, kb, tid);
        asm volatile("cp.async.commit_group;");
        slotL++;
        stepL++;
    };

    // prologue: fill NSTAGE-1 stages
    load_step();
    load_step();
    load_step();

    // ---- compute stream ----
    int slotC = 0;
    for (int jC = 0;; ++jC) {
        const int itemC = b + jC * NCTA;
        if (itemC >= NITEMS) break;
        const int ngC  = g_ngord[itemC >> 5];
        const int mtC  = itemC & 31;
        const int cntC = g_kcount[ngC];
        const int n0 = ngC << 7;
        const int m0 = mtC << 8;

        if (cntC == 0) {
            const float4* bsrc = reinterpret_cast<const float4*>(Bias + n0);
            float4* drow = reinterpret_cast<float4*>(out + (size_t)(m0 + tid) * OUT_F + n0);
#pragma unroll
            for (int c = 0; c < 32; ++c) __stcs(drow + c, bsrc[c]);
            continue;
        }

        float acc[4][8][4];
#pragma unroll
        for (int i = 0; i < 4; ++i)
#pragma unroll
            for (int j = 0; j < 8; ++j)
#pragma unroll
                for (int k = 0; k < 4; ++k) acc[i][j][k] = 0.f;

        for (int s = 0; s < cntC; ++s) {
            const int lag = slotL - slotC - 1;   // groups allowed to stay pending
            if (lag >= 2)      asm volatile("cp.async.wait_group 2;");
            else if (lag == 1) asm volatile("cp.async.wait_group 1;");
            else               asm volatile("cp.async.wait_group 0;");
            __syncthreads();
            load_step();   // writes slot (slotC-1)&3 in steady state: safe after barrier

            const uint32_t aBase = sb + (slotC & 3) * STAGE_BYTES;
            const uint32_t bBase = aBase + A_BYTES;

#pragma unroll
            for (int s16 = 0; s16 < 2; ++s16) {
                uint32_t af[4][4], bf[16];
#pragma unroll
                for (int i = 0; i < 4; ++i)
                    ldsm_x4(af[i], aBase + aOff[i][s16]);
#pragma unroll
                for (int j2 = 0; j2 < 4; ++j2)
                    ldsm_x4(bf + j2 * 4, bBase + bOff[j2][s16]);

#pragma unroll
                for (int i = 0; i < 4; ++i)
#pragma unroll
                    for (int j = 0; j < 8; ++j)
                        mma16816(acc[i][j], af[i], bf + j * 2);
            }
            slotC++;
        }

        // epilogue (streaming stores; per-warp acc, no barrier needed)
        const int cLane = (lane & 3) << 1;
        const int rLane = lane >> 2;
#pragma unroll
        for (int j = 0; j < 8; ++j) {
            const int col = n0 + (wn << 6) + (j << 3) + cLane;
            const float2 bv = *reinterpret_cast<const float2*>(Bias + col);
#pragma unroll
            for (int i = 0; i < 4; ++i) {
                const int row = m0 + (wm << 6) + (i << 4) + rLane;
                float2 o0 = make_float2(acc[i][j][0] + bv.x, acc[i][j][1] + bv.y);
                float2 o1 = make_float2(acc[i][j][2] + bv.x, acc[i][j][3] + bv.y);
                __stcs(reinterpret_cast<float2*>(out + (size_t)row * OUT_F + col), o0);
                __stcs(reinterpret_cast<float2*>(out + (size_t)(row + 8) * OUT_F + col), o1);
            }
        }
    }
}

// ---------------------------------------------------------------------------
extern "C" void kernel_launch(void* const* d_in, const int* in_sizes, int n_in,
                              void* d_out, int out_size) {
    (void)in_sizes; (void)n_in; (void)out_size;
    const float* X = (const float*)d_in[0];   // (8192, 2048)
    const float* W = (const float*)d_in[1];   // (8192, 2048)
    const float* B = (const float*)d_in[2];   // (8192,)
    float* out = (float*)d_out;               // (8192, 8192)

    cudaFuncSetAttribute(mma_kernel, cudaFuncAttributeMaxDynamicSharedMemorySize,
                         SMEM_TOTAL);

    prep1<<<12288, 256>>>(X, W);              // X convert + W block scores, fused
    topk_select<<<1, 1024>>>();
    convert_w_sel<<<TOPK, 256>>>(W);
    mma_kernel<<<NCTA, 256, SMEM_TOTAL>>>(B, out);
}

// round 16
// speedup vs baseline: 1.1909x; 1.1909x over previous
#include <cuda_runtime.h>
#include <cuda_fp16.h>
#include <cstdint>

#define IN_F   2048
#define OUT_F  8192
#define NROWS  8192
#define NBLK   4096   // 64 in-blocks (32 cols) x 64 out-blocks (128 rows)
#define TOPK   410
#define NITEMS 4096
#define NCTA   296    // persistent, 2 per SM

// ---------------------------------------------------------------------------
// Scratch (static device memory; no runtime allocation)
// ---------------------------------------------------------------------------
__device__ float g_scores[NBLK];
__device__ int   g_klist[64 * 64];
__device__ int   g_kcount[64];
__device__ int   g_ngord[64];
__device__ int   g_selkb[TOPK];
__device__ int   g_selng[TOPK];
__device__ __align__(16) unsigned short g_Xh[(size_t)NROWS * IN_F];
__device__ __align__(16) unsigned short g_Wh[(size_t)OUT_F * IN_F];

// ---------------------------------------------------------------------------
// Helpers
// ---------------------------------------------------------------------------
__device__ __forceinline__ uint32_t smem_u32(const void* p) {
    uint32_t r;
    asm("{ .reg .u64 t; cvta.to.shared.u64 t, %1; cvt.u32.u64 %0, t; }"
        : "=r"(r) : "l"(p));
    return r;
}

__device__ __forceinline__ void cp_async16(uint32_t dst, const void* src) {
    asm volatile("cp.async.cg.shared.global [%0], [%1], 16;" :: "r"(dst), "l"(src));
}

__device__ __forceinline__ void ldsm_x4(uint32_t* r, uint32_t addr) {
    asm volatile("ldmatrix.sync.aligned.m8n8.x4.shared.b16 {%0,%1,%2,%3}, [%4];"
                 : "=r"(r[0]), "=r"(r[1]), "=r"(r[2]), "=r"(r[3]) : "r"(addr));
}
__device__ __forceinline__ void mma16816(float* d, const uint32_t* a, const uint32_t* b) {
    asm volatile(
        "mma.sync.aligned.m16n8k16.row.col.f32.f16.f16.f32 "
        "{%0,%1,%2,%3}, {%4,%5,%6,%7}, {%8,%9}, {%0,%1,%2,%3};"
        : "+f"(d[0]), "+f"(d[1]), "+f"(d[2]), "+f"(d[3])
        : "r"(a[0]), "r"(a[1]), "r"(a[2]), "r"(a[3]), "r"(b[0]), "r"(b[1]));
}

// Panel: 128 rows x 64B (32 fp16), two rows per 128B line.
// 16B chunk (row, c) at: off = (row>>1)*128 + ((((row&1)<<2)+c) ^ ((row>>1)&7))*16
__device__ __forceinline__ uint32_t panel_off(int row, int c) {
    return (uint32_t)((row >> 1) * 128 +
                      (((((row & 1) << 2) + c) ^ ((row >> 1) & 7)) << 4));
}

// ---------------------------------------------------------------------------
// Kernel A: per-block sum of |W| (uniform 256-thread blocks)
// block = (i,j): 128 rows x 32 cols; thread handles half a row (16 floats)
// ---------------------------------------------------------------------------
__global__ __launch_bounds__(256)
void wscore(const float* __restrict__ W) {
    const int blk = blockIdx.x;
    const int i = blk >> 6;      // in-block
    const int j = blk & 63;      // out-block
    const int t = threadIdx.x;
    const int row = j * 128 + (t >> 1);
    const float4* p = reinterpret_cast<const float4*>(
        W + (size_t)row * IN_F + i * 32 + (t & 1) * 16);
    float s = 0.f;
#pragma unroll
    for (int c = 0; c < 4; ++c) {
        float4 v = p[c];
        s += fabsf(v.x) + fabsf(v.y) + fabsf(v.z) + fabsf(v.w);
    }
    s += __shfl_down_sync(0xFFFFFFFFu, s, 1);
    __shared__ float red[128];
    if ((t & 1) == 0) red[t >> 1] = s;
    __syncthreads();
    for (int off = 64; off > 0; off >>= 1) {
        if (t < off) red[t] += red[t + off];
        __syncthreads();
    }
    if (t == 0) g_scores[blk] = red[0];
}

// ---------------------------------------------------------------------------
// Kernel B (fused): block 0 = radix top-k (1024 threads);
// blocks 1..2048 = X fp32->fp16 convert (4 rows per block).
// topk hides under the X convert.
// ---------------------------------------------------------------------------
__global__ __launch_bounds__(1024)
void topk_convx(const float* __restrict__ X) {
    __shared__ uint32_t       keys[NBLK];
    __shared__ uint32_t       wsum[32];
    __shared__ uint32_t       s_prefix, s_k;
    __shared__ int            s_w0tot;
    __shared__ unsigned char  sel[NBLK];

    const int t    = threadIdx.x;

    if (blockIdx.x != 0) {
        // ---- X convert: chunk g = (b-1)*1024 + t handles 8 floats ----
        const size_t g = (size_t)(blockIdx.x - 1) * 1024 + t;
        const float4* s4 = reinterpret_cast<const float4*>(X) + g * 2;
        float4 a = s4[0], b = s4[1];
        __half2 h0 = __floats2half2_rn(a.x, a.y);
        __half2 h1 = __floats2half2_rn(a.z, a.w);
        __half2 h2 = __floats2half2_rn(b.x, b.y);
        __half2 h3 = __floats2half2_rn(b.z, b.w);
        uint4 o;
        o.x = *reinterpret_cast<uint32_t*>(&h0);
        o.y = *reinterpret_cast<uint32_t*>(&h1);
        o.z = *reinterpret_cast<uint32_t*>(&h2);
        o.w = *reinterpret_cast<uint32_t*>(&h3);
        reinterpret_cast<uint4*>(g_Xh)[g] = o;
        return;
    }

    // ---- block 0: radix top-k ----
    const int lane = t & 31;
    const int wid  = t >> 5;

    for (int p = t; p < NBLK; p += 1024) {
        keys[p] = __float_as_uint(g_scores[p]);   // positive: uint-orderable
        sel[p]  = 0;
    }
    if (t == 0) { s_prefix = 0; s_k = TOPK; }
    __syncthreads();

    for (int bit = 30; bit >= 0; --bit) {
        uint32_t prefix = s_prefix;
        uint32_t c = 0;
        for (int p = t; p < NBLK; p += 1024) {
            uint32_t key  = keys[p];
            bool cand = ((key ^ prefix) >> (bit + 1)) == 0;
            c += (cand && ((key >> bit) & 1u)) ? 1u : 0u;
        }
        c = __reduce_add_sync(0xFFFFFFFFu, c);
        if (lane == 0) wsum[wid] = c;
        __syncthreads();
        if (t == 0) {
            uint32_t tot = 0;
#pragma unroll
            for (int w = 0; w < 32; ++w) tot += wsum[w];
            if (tot >= s_k) s_prefix |= (1u << bit);
            else            s_k -= tot;
        }
        __syncthreads();
    }

    const uint32_t T     = s_prefix;
    const uint32_t kneed = s_k;

    uint32_t e[4], tsum = 0;
#pragma unroll
    for (int j = 0; j < 4; ++j) {
        e[j] = (keys[t * 4 + j] == T) ? 1u : 0u;
        tsum += e[j];
    }
    uint32_t x = tsum;
#pragma unroll
    for (int d = 1; d < 32; d <<= 1) {
        uint32_t y = __shfl_up_sync(0xFFFFFFFFu, x, d);
        if (lane >= d) x += y;
    }
    const uint32_t excl = x - tsum;
    if (lane == 31) wsum[wid] = x;
    __syncthreads();
    if (t == 0) {
        uint32_t run = 0;
#pragma unroll
        for (int w = 0; w < 32; ++w) { uint32_t tmp = wsum[w]; wsum[w] = run; run += tmp; }
    }
    __syncthreads();

    uint32_t r = wsum[wid] + excl;
#pragma unroll
    for (int j = 0; j < 4; ++j) {
        uint32_t key = keys[t * 4 + j];
        if (key > T) sel[t * 4 + j] = 1;
        if (e[j]) { if (r < kneed) sel[t * 4 + j] = 1; r++; }
    }
    __syncthreads();

    if (t < 64) {
        int c = 0;
        for (int i = 0; i < 64; ++i)
            if (sel[i * 64 + t]) g_klist[t * 64 + (c++)] = i;
        g_kcount[t] = c;
    }
    __syncthreads();

    // flat selected-block list (for selective W convert)
    {
        int v = (t < 64) ? g_kcount[t] : 0;
        int xx = v;
#pragma unroll
        for (int d = 1; d < 32; d <<= 1) {
            int y = __shfl_up_sync(0xFFFFFFFFu, xx, d);
            if (lane >= d) xx += y;
        }
        if (t == 31) s_w0tot = xx;
        __syncthreads();
        if (t < 64) {
            int base = (t >= 32) ? s_w0tot : 0;
            int off = base + xx - v;
            for (int i = 0; i < v; ++i) {
                g_selng[off + i] = t;
                g_selkb[off + i] = g_klist[t * 64 + i];
            }
        }
    }
    __syncthreads();

    // heavy-first n-group order
    if (t < 64) {
        const int myc = g_kcount[t];
        int rank = 0;
        for (int i = 0; i < 64; ++i) {
            const int ci = g_kcount[i];
            rank += (ci > myc) || (ci == myc && i < t);
        }
        g_ngord[rank] = t;
    }
}

// ---------------------------------------------------------------------------
// Kernel C: convert ONLY selected W blocks to fp16 (grid = TOPK)
// ---------------------------------------------------------------------------
__global__ __launch_bounds__(256)
void convert_w_sel(const float* __restrict__ W) {
    const int kb = g_selkb[blockIdx.x];
    const int ng = g_selng[blockIdx.x];
    const int tid = threadIdx.x;
#pragma unroll
    for (int u = 0; u < 4; ++u) {
        const int q   = tid + (u << 8);
        const int row = q >> 3;
        const int cc  = q & 7;
        const size_t grow = (size_t)(ng * 128 + row);
        float4 v = *reinterpret_cast<const float4*>(W + grow * IN_F + kb * 32 + cc * 4);
        __half2 h0 = __floats2half2_rn(v.x, v.y);
        __half2 h1 = __floats2half2_rn(v.z, v.w);
        uint2 o;
        o.x = *reinterpret_cast<uint32_t*>(&h0);
        o.y = *reinterpret_cast<uint32_t*>(&h1);
        *reinterpret_cast<uint2*>(g_Wh + grow * IN_F + kb * 32 + cc * 4) = o;
    }
}

// ---------------------------------------------------------------------------
// Kernel D: PERSISTENT block-sparse GEMM (R14 config: best measured).
// 296 CTAs, CTA tile 128x128, 4 warps, warp tile 64x64, 4-stage pipeline,
// continuous cp.async cursor across item boundaries. load_step issued after
// phase-0 MMAs to overlap LDGSTS issue with tensor issue.
// ---------------------------------------------------------------------------
#define AS_OFF      0
#define BS_OFF      8192
#define STAGE_BYTES 16384
#define NSTAGE      4
#define SMEM_TOTAL  (STAGE_BYTES * NSTAGE)

__device__ __forceinline__ void load_tiles(uint32_t stage_base,
                                           const uint4* __restrict__ XH,
                                           const uint4* __restrict__ WH,
                                           int m0, int n0, int kb, int tid) {
    const int kb4 = kb * 4;
#pragma unroll
    for (int j = 0; j < 4; ++j) {
        int q   = tid + (j << 7);           // 0..511 chunks per panel
        int row = q >> 2;
        int c   = q & 3;
        uint32_t off = panel_off(row, c);
        cp_async16(stage_base + AS_OFF + off, XH + (size_t)(m0 + row) * 256 + kb4 + c);
        cp_async16(stage_base + BS_OFF + off, WH + (size_t)(n0 + row) * 256 + kb4 + c);
    }
}

__global__ __launch_bounds__(128, 2)
void mma_kernel(const float* __restrict__ Bias, float* __restrict__ out) {
    extern __shared__ char smem[];
    const uint32_t sb  = smem_u32(smem);
    const int tid  = threadIdx.x;
    const int wid  = tid >> 5;
    const int lane = tid & 31;
    const int b    = blockIdx.x;

    const int wm = wid & 1;        // m half (64 rows)
    const int wn = wid >> 1;       // n half (64 cols)

    // per-lane fragment offsets (item-independent)
    uint32_t aOff[4][2];
#pragma unroll
    for (int i = 0; i < 4; ++i) {
        const int rowA = (wm << 6) + (i << 4) + (lane & 15);
#pragma unroll
        for (int s16 = 0; s16 < 2; ++s16)
            aOff[i][s16] = panel_off(rowA, (s16 << 1) + (lane >> 4));
    }
    uint32_t bOff[4][2];
#pragma unroll
    for (int j2 = 0; j2 < 4; ++j2) {
        const int rowB = (wn << 6) + (j2 << 4) + (((lane >> 4) & 1) << 3) + (lane & 7);
#pragma unroll
        for (int s16 = 0; s16 < 2; ++s16)
            bOff[j2][s16] = panel_off(rowB, (s16 << 1) + ((lane >> 3) & 1));
    }

    const uint4* XH = reinterpret_cast<const uint4*>(g_Xh);
    const uint4* WH = reinterpret_cast<const uint4*>(g_Wh);

    // ---- load cursor (uniform across threads) ----
    int jL    = 0;
    int itemL = b;
    int ngL   = g_ngord[itemL >> 6];
    int mtL   = itemL & 63;
    int cntL  = g_kcount[ngL];
    int stepL = 0;
    int slotL = 0;

    auto load_step = [&]() {
        while (stepL >= cntL) {
            jL++;
            itemL = b + jL * NCTA;
            if (itemL >= NITEMS) return;
            ngL  = g_ngord[itemL >> 6];
            mtL  = itemL & 63;
            cntL = g_kcount[ngL];
            stepL = 0;
        }
        const int kb = g_klist[(ngL << 6) + stepL];
        load_tiles(sb + (slotL & 3) * STAGE_BYTES, XH, WH, mtL << 7, ngL << 7, kb, tid);
        asm volatile("cp.async.commit_group;");
        slotL++;
        stepL++;
    };

    // prologue: fill NSTAGE-1 stages
    load_step();
    load_step();
    load_step();

    // ---- compute stream ----
    int slotC = 0;
    for (int jC = 0;; ++jC) {
        const int itemC = b + jC * NCTA;
        if (itemC >= NITEMS) break;
        const int ngC  = g_ngord[itemC >> 6];
        const int mtC  = itemC & 63;
        const int cntC = g_kcount[ngC];
        const int n0 = ngC << 7;
        const int m0 = mtC << 7;

        if (cntC == 0) {
            const float4* bsrc = reinterpret_cast<const float4*>(Bias + n0);
            float4* drow = reinterpret_cast<float4*>(out + (size_t)(m0 + tid) * OUT_F + n0);
#pragma unroll
            for (int c = 0; c < 32; ++c) __stcs(drow + c, bsrc[c]);
            continue;
        }

        float acc[4][8][4];
#pragma unroll
        for (int i = 0; i < 4; ++i)
#pragma unroll
            for (int j = 0; j < 8; ++j)
#pragma unroll
                for (int k = 0; k < 4; ++k) acc[i][j][k] = 0.f;

        for (int s = 0; s < cntC; ++s) {
            const int lag = slotL - slotC - 1;
            if (lag >= 2)      asm volatile("cp.async.wait_group 2;");
            else if (lag == 1) asm volatile("cp.async.wait_group 1;");
            else               asm volatile("cp.async.wait_group 0;");
            __syncthreads();

            const uint32_t aBase = sb + (slotC & 3) * STAGE_BYTES + AS_OFF;
            const uint32_t bBase = sb + (slotC & 3) * STAGE_BYTES + BS_OFF;

            // ---- phase 0: ldsm + mma ----
            {
                uint32_t af[4][4], bf[16];
#pragma unroll
                for (int i = 0; i < 4; ++i)
                    ldsm_x4(af[i], aBase + aOff[i][0]);
#pragma unroll
                for (int j2 = 0; j2 < 4; ++j2)
                    ldsm_x4(bf + j2 * 4, bBase + bOff[j2][0]);
#pragma unroll
                for (int i = 0; i < 4; ++i)
#pragma unroll
                    for (int j = 0; j < 8; ++j)
                        mma16816(acc[i][j], af[i], bf + j * 2);
            }

            // overlap next stage's LDGSTS issue under tensor work
            load_step();   // targets slot (slotC-1)&3: safe after the barrier

            // ---- phase 1: ldsm + mma ----
            {
                uint32_t af[4][4], bf[16];
#pragma unroll
                for (int i = 0; i < 4; ++i)
                    ldsm_x4(af[i], aBase + aOff[i][1]);
#pragma unroll
                for (int j2 = 0; j2 < 4; ++j2)
                    ldsm_x4(bf + j2 * 4, bBase + bOff[j2][1]);
#pragma unroll
                for (int i = 0; i < 4; ++i)
#pragma unroll
                    for (int j = 0; j < 8; ++j)
                        mma16816(acc[i][j], af[i], bf + j * 2);
            }
            slotC++;
        }

        // epilogue (streaming stores; per-warp acc, no barrier needed)
        const int cLane = (lane & 3) << 1;
        const int rLane = lane >> 2;
#pragma unroll
        for (int j = 0; j < 8; ++j) {
            const int col = n0 + (wn << 6) + (j << 3) + cLane;
            const float2 bv = *reinterpret_cast<const float2*>(Bias + col);
#pragma unroll
            for (int i = 0; i < 4; ++i) {
                const int row = m0 + (wm << 6) + (i << 4) + rLane;
                float2 o0 = make_float2(acc[i][j][0] + bv.x, acc[i][j][1] + bv.y);
                float2 o1 = make_float2(acc[i][j][2] + bv.x, acc[i][j][3] + bv.y);
                __stcs(reinterpret_cast<float2*>(out + (size_t)row * OUT_F + col), o0);
                __stcs(reinterpret_cast<float2*>(out + (size_t)(row + 8) * OUT_F + col), o1);
            }
        }
    }
}

// ---------------------------------------------------------------------------
extern "C" void kernel_launch(void* const* d_in, const int* in_sizes, int n_in,
                              void* d_out, int out_size) {
    (void)in_sizes; (void)n_in; (void)out_size;
    const float* X = (const float*)d_in[0];   // (8192, 2048)
    const float* W = (const float*)d_in[1];   // (8192, 2048)
    const float* B = (const float*)d_in[2];   // (8192,)
    float* out = (float*)d_out;               // (8192, 8192)

    cudaFuncSetAttribute(mma_kernel, cudaFuncAttributeMaxDynamicSharedMemorySize,
                         SMEM_TOTAL);

    wscore<<<NBLK, 256>>>(W);                 // per-block |W| sums
    topk_convx<<<2049, 1024>>>(X);            // topk (block 0) || X convert
    convert_w_sel<<<TOPK, 256>>>(W);          // only selected blocks
    mma_kernel<<<NCTA, 128, SMEM_TOTAL>>>(B, out);
}